// round 3
// baseline (speedup 1.0000x reference)
#include <cuda_runtime.h>
#include <math.h>

#define B_ 64
#define T_ 512
#define H_ 256
#define G_ 1024
#define BH_ (B_*H_)

// ---------------- static device scratch (no allocations) ----------------
__device__ float g_x [(size_t)T_*B_*256];   // x,  row m = t*64+b
__device__ float g_gx[(size_t)T_*B_*G_];    // gx, row m = t*64+b
__device__ float g_h [(size_t)(T_+1)*BH_];  // h history [(T+1), B, H]
__device__ float g_c [(size_t)(T_+1)*BH_];  // c history

typedef unsigned long long u64;
typedef unsigned int u32;

// ---------------- f32x2 helpers ----------------
__device__ __forceinline__ u64 fma2(u64 a, u64 b, u64 c){
    u64 d; asm("fma.rn.f32x2 %0, %1, %2, %3;" : "=l"(d) : "l"(a), "l"(b), "l"(c)); return d;
}
__device__ __forceinline__ u64 pack2(float x, float y){
    u64 d; asm("mov.b64 %0, {%1, %2};" : "=l"(d)
               : "r"(__float_as_uint(x)), "r"(__float_as_uint(y))); return d;
}
__device__ __forceinline__ float2 unp2(u64 v){
    u32 lo, hi; asm("mov.b64 {%0, %1}, %2;" : "=r"(lo), "=r"(hi) : "l"(v));
    return make_float2(__uint_as_float(lo), __uint_as_float(hi));
}
__device__ __forceinline__ float sigm(float x){ return 1.0f/(1.0f + __expf(-x)); }

// ---------------- init: zero the t=0 slots of h/c history ----------------
__global__ void init_hc(){
    int i = blockIdx.x*256 + threadIdx.x;
    if(i < BH_){ g_h[i] = 0.0f; g_c[i] = 0.0f; }
}

// ---------------- embedding gather + mean + concat ----------------
__global__ __launch_bounds__(128)
void embed_kernel(const int* __restrict__ node, const int* __restrict__ rel,
                  const float* __restrict__ emb)
{
    int pos  = blockIdx.x*4 + (threadIdx.x >> 5);   // pos = b*T + t
    int lane = threadIdx.x & 31;
    int b = pos >> 9, t = pos & 511;
    const float4* E = (const float4*)emb;           // EMB=128 floats = 32 float4
    int n0 = __ldg(&node[pos*2+0]);
    int n1 = __ldg(&node[pos*2+1]);
    int r0 = __ldg(&rel[pos*3+0]);
    int r1 = __ldg(&rel[pos*3+1]);
    int r2 = __ldg(&rel[pos*3+2]);
    float4 e0 = __ldg(&E[(size_t)n0*32 + lane]);
    float4 e1 = __ldg(&E[(size_t)n1*32 + lane]);
    float4 f0 = __ldg(&E[(size_t)r0*32 + lane]);
    float4 f1 = __ldg(&E[(size_t)r1*32 + lane]);
    float4 f2 = __ldg(&E[(size_t)r2*32 + lane]);
    float4 nv = make_float4(0.5f*(e0.x+e1.x), 0.5f*(e0.y+e1.y),
                            0.5f*(e0.z+e1.z), 0.5f*(e0.w+e1.w));
    const float th = (1.0f/3.0f);
    float4 rv = make_float4(th*(f0.x+f1.x+f2.x), th*(f0.y+f1.y+f2.y),
                            th*(f0.z+f1.z+f2.z), th*(f0.w+f1.w+f2.w));
    float4* xr = (float4*)(g_x + ((size_t)t*B_ + b)*256);   // t-major rows
    xr[lane]      = nv;     // node_e -> cols [0,128)
    xr[32 + lane] = rv;     // rel_e  -> cols [128,256)
}

// ---------------- SGEMM (NT): C[M,N] = A[M,K] * Bw[N,K]^T (+ bias[N]) ----------------
// 128x128 tile, BK=16, 256 threads, 8x8 microtile on f32x2 pairs.
__global__ __launch_bounds__(256)
void sgemm_nt(const float* __restrict__ A, const float* __restrict__ Bw,
              const float* __restrict__ bias, float* __restrict__ C,
              int M, int N, int K)
{
    __shared__ __align__(16) float As[16][128];
    __shared__ __align__(16) float Bs[16][128];
    int tid = threadIdx.x;
    int m0 = blockIdx.y * 128;
    int n0 = blockIdx.x * 128;
    int tx = tid & 15, ty = tid >> 4;

    u64 acc[8][4];
#pragma unroll
    for(int i=0;i<8;i++)
#pragma unroll
        for(int j=0;j<4;j++) acc[i][j] = 0ull;

    for(int kt=0; kt<K; kt+=16){
#pragma unroll
        for(int s=0;s<2;s++){
            int id  = tid + s*256;
            int row = id & 127;
            int kq  = id >> 7;      // 0..3
            float4 av = __ldg((const float4*)(A  + (size_t)(m0+row)*K + kt + kq*4));
            As[kq*4+0][row]=av.x; As[kq*4+1][row]=av.y;
            As[kq*4+2][row]=av.z; As[kq*4+3][row]=av.w;
            float4 bv = __ldg((const float4*)(Bw + (size_t)(n0+row)*K + kt + kq*4));
            Bs[kq*4+0][row]=bv.x; Bs[kq*4+1][row]=bv.y;
            Bs[kq*4+2][row]=bv.z; Bs[kq*4+3][row]=bv.w;
        }
        __syncthreads();
#pragma unroll
        for(int k=0;k<16;k++){
            float4 a0 = *(const float4*)&As[k][ty*8];
            float4 a1 = *(const float4*)&As[k][ty*8+4];
            const u64* bp = (const u64*)&Bs[k][tx*8];
            u64 b0=bp[0], b1=bp[1], b2=bp[2], b3=bp[3];
            float af[8] = {a0.x,a0.y,a0.z,a0.w,a1.x,a1.y,a1.z,a1.w};
#pragma unroll
            for(int i=0;i<8;i++){
                u64 aa = pack2(af[i], af[i]);
                acc[i][0] = fma2(aa, b0, acc[i][0]);
                acc[i][1] = fma2(aa, b1, acc[i][1]);
                acc[i][2] = fma2(aa, b2, acc[i][2]);
                acc[i][3] = fma2(aa, b3, acc[i][3]);
            }
        }
        __syncthreads();
    }
#pragma unroll
    for(int i=0;i<8;i++){
        float* cp = C + (size_t)(m0 + ty*8 + i)*N + n0 + tx*8;
#pragma unroll
        for(int j=0;j<4;j++){
            float2 v = unp2(acc[i][j]);
            if(bias){
                v.x += __ldg(&bias[n0 + tx*8 + 2*j    ]);
                v.y += __ldg(&bias[n0 + tx*8 + 2*j + 1]);
            }
            ((float2*)cp)[j] = v;
        }
    }
}

// ---------------- serial tree-LSTM scan ----------------
// 16 clusters of 8 CTAs. Cluster c owns batches [4c,4c+4); CTA rank r owns hidden
// units [32r,32r+32) -> 128 gate rows, W_hh slice register-resident (128 f/thread).
// Thread layout: kidx = tid&7 (K-chunk of 32), rg = tid>>3 (4 rows each).
__global__ __launch_bounds__(256, 1) __cluster_dims__(8, 1, 1)
void scan_kernel(const int* __restrict__ father, const float* __restrict__ mask,
                 const float* __restrict__ W_hh, const float* __restrict__ b_hh,
                 float* __restrict__ out)
{
    __shared__ __align__(16) float sh[4*272];      // h_prev: 4 batches, 8 chunks x 34f (pad)
    __shared__ float s_gates[4*128];

    int tid  = threadIdx.x;
    int rank = blockIdx.x & 7;
    int cid  = blockIdx.x >> 3;
    int u0   = rank * 32;
    int kidx = tid & 7;
    int rg   = tid >> 3;

    // register-resident W_hh slice: 4 rows x 32 K-floats (as 16 u64 pairs each)
    u64   w2[64];
    float bh[4];
    int   grow_[4];
#pragma unroll
    for(int rj=0; rj<4; rj++){
        int lr   = rg*4 + rj;                        // 0..127
        int grow = (lr>>5)*256 + u0 + (lr&31);       // gate*256 + unit
        grow_[rj] = grow;
        bh[rj]    = __ldg(&b_hh[grow]);
        const u64* Wp = (const u64*)(W_hh + (size_t)grow*256 + kidx*32);
#pragma unroll
        for(int i=0;i<16;i++) w2[rj*16+i] = __ldg(&Wp[i]);
    }

    int sb = tid >> 6;            // staging batch 0..3
    int k4 = (tid & 63) * 4;      // staging k offset
    int bg_s = cid*4 + sb;
    int cb = tid >> 5;            // cell batch (tid<128)
    int cu = tid & 31;            // cell unit
    int bg_c = cid*4 + cb;

    float hmx = -1e30f, cmx = -1e30f;

    for(int t=0; t<T_; t++){
        // ---- stage h_prev (father-gather) into padded shared ----
        int fs  = __ldg(&father[bg_s*T_ + t]);
        int idx = min(fs, t-1) + 1;                  // in [0, t]
        float4 hv = __ldcg((const float4*)(g_h + (size_t)idx*BH_ + bg_s*H_ + k4));
        {
            int chunk = k4 >> 5, w = k4 & 31;
            float* dst = sh + sb*272 + chunk*34 + w;
            dst[0]=hv.x; dst[1]=hv.y; dst[2]=hv.z; dst[3]=hv.w;
        }
        // ---- prefetch gx rows for combiner threads ----
        float gxv[16];
        if(kidx == 0){
#pragma unroll
            for(int rj=0; rj<4; rj++){
                const float* gp = g_gx + ((size_t)t*B_ + cid*4)*G_ + grow_[rj];
#pragma unroll
                for(int b=0;b<4;b++) gxv[rj*4+b] = __ldg(gp + b*G_);
            }
        }
        __syncthreads();

        // ---- partial dot products (f32x2) ----
        float p[16];
#pragma unroll
        for(int b=0;b<4;b++){
            const u64* hq = (const u64*)(sh + b*272 + kidx*34);
            u64 a0=0ull, a1=0ull, a2=0ull, a3=0ull;
#pragma unroll
            for(int i=0;i<16;i++){
                u64 hh = hq[i];
                a0 = fma2(w2[     i], hh, a0);
                a1 = fma2(w2[16 + i], hh, a1);
                a2 = fma2(w2[32 + i], hh, a2);
                a3 = fma2(w2[48 + i], hh, a3);
            }
            float2 r0=unp2(a0), r1=unp2(a1), r2=unp2(a2), r3=unp2(a3);
            p[0 +b] = r0.x+r0.y; p[4 +b] = r1.x+r1.y;
            p[8 +b] = r2.x+r2.y; p[12+b] = r3.x+r3.y;
        }
        // ---- butterfly reduce across the 8 kidx lanes ----
#pragma unroll
        for(int m=1;m<8;m<<=1){
#pragma unroll
            for(int v=0;v<16;v++) p[v] += __shfl_xor_sync(0xffffffffu, p[v], m);
        }
        if(kidx == 0){
#pragma unroll
            for(int rj=0;rj<4;rj++){
                int lr = rg*4 + rj;
#pragma unroll
                for(int b=0;b<4;b++)
                    s_gates[b*128 + lr] = p[rj*4+b] + gxv[rj*4+b] + bh[rj];
            }
        }
        __syncthreads();

        // ---- LSTM cell (32 units x 4 batches = 128 threads) ----
        if(tid < 128){
            float gi = s_gates[cb*128 +       cu];
            float gf = s_gates[cb*128 + 32  + cu];
            float gg = s_gates[cb*128 + 64  + cu];
            float go = s_gates[cb*128 + 96  + cu];
            int fc  = __ldg(&father[bg_c*T_ + t]);
            int idc = min(fc, t-1) + 1;
            float cp = __ldcg(&g_c[(size_t)idc*BH_ + bg_c*H_ + u0 + cu]);
            float cv  = sigm(gf)*cp + sigm(gi)*tanhf(gg);
            float hv2 = sigm(go)*tanhf(cv);
            size_t o = (size_t)(t+1)*BH_ + bg_c*H_ + u0 + cu;
            g_h[o] = hv2; g_c[o] = cv;
            float mv = __ldg(&mask[bg_c*T_ + t]);
            float hm = hv2*mv;
            out[(size_t)bg_c*(T_*H_) + (size_t)t*H_ + u0 + cu] = hm;  // encoder_outputs
            hmx = fmaxf(hmx, hm);
            cmx = fmaxf(cmx, cv*mv);
        }
        __threadfence();
        asm volatile("barrier.cluster.arrive.aligned;" ::: "memory");
        asm volatile("barrier.cluster.wait.aligned;"   ::: "memory");
    }

    if(tid < 128){
        size_t base = (size_t)2*B_*T_*H_;     // after enc_outputs + enc_feature
        out[base +        bg_c*H_ + u0 + cu] = hmx;   // h_max
        out[base + BH_ +  bg_c*H_ + u0 + cu] = cmx;   // c_max
    }
}

extern "C" void kernel_launch(void* const* d_in, const int* in_sizes, int n_in,
                              void* d_out, int out_size)
{
    const int*   node   = (const int*)  d_in[0];
    const int*   rel    = (const int*)  d_in[1];
    const int*   father = (const int*)  d_in[2];
    const float* mask   = (const float*)d_in[3];
    const float* emb    = (const float*)d_in[4];
    const float* W_ih   = (const float*)d_in[5];
    const float* W_hh   = (const float*)d_in[6];
    const float* b_ih   = (const float*)d_in[7];
    const float* b_hh   = (const float*)d_in[8];
    const float* W_h    = (const float*)d_in[9];
    float* out = (float*)d_out;

    float *px, *pgx;
    cudaGetSymbolAddress((void**)&px,  g_x);
    cudaGetSymbolAddress((void**)&pgx, g_gx);

    init_hc<<<(BH_+255)/256, 256>>>();
    embed_kernel<<<(B_*T_)/4, 128>>>(node, rel, emb);

    dim3 g1(G_/128, (B_*T_)/128);                    // (8, 256)
    sgemm_nt<<<g1, 256>>>(px, W_ih, b_ih, pgx, B_*T_, G_, 256);

    scan_kernel<<<128, 256>>>(father, mask, W_hh, b_hh, out);

    dim3 g2(H_/128, (B_*T_)/128);                    // (2, 256)
    sgemm_nt<<<g2, 256>>>(out, W_h, (const float*)nullptr,
                          out + (size_t)B_*T_*H_, B_*T_, H_, 256);
}

// round 4
// speedup vs baseline: 1.0148x; 1.0148x over previous
#include <cuda_runtime.h>
#include <math.h>

#define B_ 64
#define T_ 512
#define H_ 256
#define G_ 1024
#define BH_ (B_*H_)

// ---------------- static device scratch (no allocations) ----------------
__device__ float g_x [(size_t)T_*B_*256];   // x,  row m = t*64+b
__device__ float g_gx[(size_t)T_*B_*G_];    // gx, row m = t*64+b
__device__ float g_h [(size_t)(T_+1)*BH_];  // h history [(T+1), B, H]
__device__ float g_c [(size_t)(T_+1)*BH_];  // c history

typedef unsigned long long u64;
typedef unsigned int u32;

// ---------------- f32x2 helpers ----------------
__device__ __forceinline__ u64 fma2(u64 a, u64 b, u64 c){
    u64 d; asm("fma.rn.f32x2 %0, %1, %2, %3;" : "=l"(d) : "l"(a), "l"(b), "l"(c)); return d;
}
__device__ __forceinline__ u64 pack2(float x, float y){
    u64 d; asm("mov.b64 %0, {%1, %2};" : "=l"(d)
               : "r"(__float_as_uint(x)), "r"(__float_as_uint(y))); return d;
}
__device__ __forceinline__ float2 unp2(u64 v){
    u32 lo, hi; asm("mov.b64 {%0, %1}, %2;" : "=r"(lo), "=r"(hi) : "l"(v));
    return make_float2(__uint_as_float(lo), __uint_as_float(hi));
}
__device__ __forceinline__ float sigm(float x){ return 1.0f/(1.0f + __expf(-x)); }

__device__ __forceinline__ void st_cluster_f32(u32 saddr, int rank, float v){
    u32 r;
    asm volatile("mapa.shared::cluster.u32 %0, %1, %2;" : "=r"(r) : "r"(saddr), "r"(rank));
    asm volatile("st.shared::cluster.f32 [%0], %1;" :: "r"(r), "f"(v));
}

#define CARRIVE() asm volatile("barrier.cluster.arrive.aligned;" ::: "memory")
#define CWAIT()   asm volatile("barrier.cluster.wait.aligned;"   ::: "memory")

// ---------------- embedding gather + mean + concat ----------------
__global__ __launch_bounds__(128)
void embed_kernel(const int* __restrict__ node, const int* __restrict__ rel,
                  const float* __restrict__ emb)
{
    int pos  = blockIdx.x*4 + (threadIdx.x >> 5);   // pos = b*T + t
    int lane = threadIdx.x & 31;
    int b = pos >> 9, t = pos & 511;
    const float4* E = (const float4*)emb;           // EMB=128 floats = 32 float4
    int n0 = __ldg(&node[pos*2+0]);
    int n1 = __ldg(&node[pos*2+1]);
    int r0 = __ldg(&rel[pos*3+0]);
    int r1 = __ldg(&rel[pos*3+1]);
    int r2 = __ldg(&rel[pos*3+2]);
    float4 e0 = __ldg(&E[(size_t)n0*32 + lane]);
    float4 e1 = __ldg(&E[(size_t)n1*32 + lane]);
    float4 f0 = __ldg(&E[(size_t)r0*32 + lane]);
    float4 f1 = __ldg(&E[(size_t)r1*32 + lane]);
    float4 f2 = __ldg(&E[(size_t)r2*32 + lane]);
    float4 nv = make_float4(0.5f*(e0.x+e1.x), 0.5f*(e0.y+e1.y),
                            0.5f*(e0.z+e1.z), 0.5f*(e0.w+e1.w));
    const float th = (1.0f/3.0f);
    float4 rv = make_float4(th*(f0.x+f1.x+f2.x), th*(f0.y+f1.y+f2.y),
                            th*(f0.z+f1.z+f2.z), th*(f0.w+f1.w+f2.w));
    float4* xr = (float4*)(g_x + ((size_t)t*B_ + b)*256);   // t-major rows
    xr[lane]      = nv;
    xr[32 + lane] = rv;
}

// ---------------- SGEMM (NT): C[M,N] = A[M,K] * Bw[N,K]^T (+ bias[N]) ----------------
__global__ __launch_bounds__(256)
void sgemm_nt(const float* __restrict__ A, const float* __restrict__ Bw,
              const float* __restrict__ bias, float* __restrict__ C,
              int M, int N, int K)
{
    __shared__ __align__(16) float As[16][128];
    __shared__ __align__(16) float Bs[16][128];
    int tid = threadIdx.x;
    int m0 = blockIdx.y * 128;
    int n0 = blockIdx.x * 128;
    int tx = tid & 15, ty = tid >> 4;

    u64 acc[8][4];
#pragma unroll
    for(int i=0;i<8;i++)
#pragma unroll
        for(int j=0;j<4;j++) acc[i][j] = 0ull;

    for(int kt=0; kt<K; kt+=16){
#pragma unroll
        for(int s=0;s<2;s++){
            int id  = tid + s*256;
            int row = id & 127;
            int kq  = id >> 7;      // 0..3
            float4 av = __ldg((const float4*)(A  + (size_t)(m0+row)*K + kt + kq*4));
            As[kq*4+0][row]=av.x; As[kq*4+1][row]=av.y;
            As[kq*4+2][row]=av.z; As[kq*4+3][row]=av.w;
            float4 bv = __ldg((const float4*)(Bw + (size_t)(n0+row)*K + kt + kq*4));
            Bs[kq*4+0][row]=bv.x; Bs[kq*4+1][row]=bv.y;
            Bs[kq*4+2][row]=bv.z; Bs[kq*4+3][row]=bv.w;
        }
        __syncthreads();
#pragma unroll
        for(int k=0;k<16;k++){
            float4 a0 = *(const float4*)&As[k][ty*8];
            float4 a1 = *(const float4*)&As[k][ty*8+4];
            const u64* bp = (const u64*)&Bs[k][tx*8];
            u64 b0=bp[0], b1=bp[1], b2=bp[2], b3=bp[3];
            float af[8] = {a0.x,a0.y,a0.z,a0.w,a1.x,a1.y,a1.z,a1.w};
#pragma unroll
            for(int i=0;i<8;i++){
                u64 aa = pack2(af[i], af[i]);
                acc[i][0] = fma2(aa, b0, acc[i][0]);
                acc[i][1] = fma2(aa, b1, acc[i][1]);
                acc[i][2] = fma2(aa, b2, acc[i][2]);
                acc[i][3] = fma2(aa, b3, acc[i][3]);
            }
        }
        __syncthreads();
    }
#pragma unroll
    for(int i=0;i<8;i++){
        float* cp = C + (size_t)(m0 + ty*8 + i)*N + n0 + tx*8;
#pragma unroll
        for(int j=0;j<4;j++){
            float2 v = unp2(acc[i][j]);
            if(bias){
                v.x += __ldg(&bias[n0 + tx*8 + 2*j    ]);
                v.y += __ldg(&bias[n0 + tx*8 + 2*j + 1]);
            }
            ((float2*)cp)[j] = v;
        }
    }
}

// ---------------- serial tree-LSTM scan ----------------
// 16 clusters x 8 CTAs. Cluster c: batches [4c,4c+4). CTA rank r: units [32r,32r+32).
// Prefetch pipeline: OLD (idx<=t-2) h gathers prefetched from global one step early;
// SEMI (idx==t-1) / FRESH (idx==t) read the DSMEM-pushed ring (local smem).
// Dots for OLD/SEMI run BEFORE barrier.cluster.wait to hide the barrier.
__global__ __launch_bounds__(256, 1) __cluster_dims__(8, 1, 1)
void scan_kernel(const int* __restrict__ father, const float* __restrict__ mask,
                 const float* __restrict__ W_hh, const float* __restrict__ b_hh,
                 float* __restrict__ out)
{
    __shared__ __align__(16) float sh[4*272];       // prefetched-h staging (padded)
    __shared__ __align__(16) float fbuf[3][4*272];  // DSMEM fresh-h ring (same layout)
    __shared__ float s_gates[4*128];
    __shared__ int   s_flag[2][4];                  // 0=OLD 1=SEMI 2=FRESH, per batch

    int tid  = threadIdx.x;
    int rank = blockIdx.x & 7;
    int cid  = blockIdx.x >> 3;
    int u0   = rank * 32;
    int kidx = tid & 7;
    int rg   = tid >> 3;

    // register-resident W_hh slice: 4 gate rows x 32 K-floats (16 u64 each)
    u64   w2[64];
    float bh[4];
    int   grow_[4];
#pragma unroll
    for(int rj=0; rj<4; rj++){
        int lr   = rg*4 + rj;
        int grow = (lr>>5)*256 + u0 + (lr&31);
        grow_[rj] = grow;
        bh[rj]    = __ldg(&b_hh[grow]);
        const u64* Wp = (const u64*)(W_hh + (size_t)grow*256 + kidx*32);
#pragma unroll
        for(int i=0;i<16;i++) w2[rj*16+i] = __ldg(&Wp[i]);
    }

    int sb   = tid >> 6;           // staging batch 0..3
    int k4   = (tid & 63) * 4;     // staging unit offset
    int bg_s = cid*4 + sb;
    int cb   = tid >> 5;           // cell batch (tid<128)
    int cu   = tid & 31;           // cell unit
    int bg_c = cid*4 + cb;

    float hmx = -1e30f, cmx = -1e30f;

    // pipeline state
    float4 pf   = make_float4(0.f,0.f,0.f,0.f);  // prefetched h (OLD case)
    int    flcur = 0;                             // this thread's batch flag for step t
    float  c_pf = 0.f, c_last = 0.f;
    int    cfl  = 0;                              // c fresh flag for step t

    if(tid < 4){ s_flag[0][tid] = 0; }
    __syncthreads();
    CARRIVE();                                    // pairs with wait at t=0

    for(int t=0; t<T_; t++){
        // (1) stage prefetched h into sh (OLD batches only)
        if(flcur == 0){
            float* dst = sh + sb*272 + (k4>>5)*34 + (k4&31);
            dst[0]=pf.x; dst[1]=pf.y; dst[2]=pf.z; dst[3]=pf.w;
        }
        // (2) prefetch for step t+1 + gx for current step
        if(t+1 < T_){
            int f   = __ldg(&father[bg_s*T_ + t+1]);
            int idx = min(f, t) + 1;              // clip for step t+1
            flcur = (idx == t+1) ? 2 : ((idx == t) ? 1 : 0);
            if(flcur == 0)
                pf = __ldcg((const float4*)(g_h + (size_t)idx*BH_ + bg_s*H_ + k4));
            if((tid & 63) == 0) s_flag[(t+1)&1][sb] = flcur;
        }
        float gxv[16];
        if(kidx == 0){
#pragma unroll
            for(int rj=0; rj<4; rj++){
                const float* gp = g_gx + ((size_t)t*B_ + cid*4)*G_ + grow_[rj];
#pragma unroll
                for(int b=0;b<4;b++) gxv[rj*4+b] = __ldg(gp + b*G_);
            }
        }
        __syncthreads();   // (3)

        // dot-product lambda for one batch
        auto dotb = [&](int b, const float* hb){
            const u64* hq = (const u64*)(hb + kidx*34);
            u64 a0=0ull, a1=0ull, a2=0ull, a3=0ull;
#pragma unroll
            for(int i=0;i<16;i++){
                u64 hh = hq[i];
                a0 = fma2(w2[     i], hh, a0);
                a1 = fma2(w2[16 + i], hh, a1);
                a2 = fma2(w2[32 + i], hh, a2);
                a3 = fma2(w2[48 + i], hh, a3);
            }
            float2 r0=unp2(a0), r1=unp2(a1), r2=unp2(a2), r3=unp2(a3);
            float q0=r0.x+r0.y, q1=r1.x+r1.y, q2=r2.x+r2.y, q3=r3.x+r3.y;
#pragma unroll
            for(int m=1;m<8;m<<=1){
                q0 += __shfl_xor_sync(0xffffffffu, q0, m);
                q1 += __shfl_xor_sync(0xffffffffu, q1, m);
                q2 += __shfl_xor_sync(0xffffffffu, q2, m);
                q3 += __shfl_xor_sync(0xffffffffu, q3, m);
            }
            if(kidx == 0){
                s_gates[b*128 + rg*4 + 0] = q0 + gxv[0*4+b] + bh[0];
                s_gates[b*128 + rg*4 + 1] = q1 + gxv[1*4+b] + bh[1];
                s_gates[b*128 + rg*4 + 2] = q2 + gxv[2*4+b] + bh[2];
                s_gates[b*128 + rg*4 + 3] = q3 + gxv[3*4+b] + bh[3];
            }
        };

        // (4) phase A: OLD (sh) + SEMI (fbuf[(t+2)%3], pushed 2 steps ago) — no wait needed
#pragma unroll
        for(int b=0;b<4;b++){
            int fl = s_flag[t&1][b];
            if(fl == 2) continue;
            const float* hb = (fl == 0) ? (sh + b*272) : (&fbuf[(t+2)%3][0] + b*272);
            dotb(b, hb);
        }
        CWAIT();           // (5) acquire peers' pushes + global h stores
        // (6) phase B: FRESH (fbuf[t%3], pushed last step)
#pragma unroll
        for(int b=0;b<4;b++){
            if(s_flag[t&1][b] != 2) continue;
            dotb(b, &fbuf[t%3][0] + b*272);
        }
        __syncthreads();   // (7)

        // (8) LSTM cell
        if(tid < 128){
            float gi = s_gates[cb*128 +      cu];
            float gf = s_gates[cb*128 + 32 + cu];
            float gg = s_gates[cb*128 + 64 + cu];
            float go = s_gates[cb*128 + 96 + cu];
            float cprev = cfl ? c_last : c_pf;
            float cv  = sigm(gf)*cprev + sigm(gi)*tanhf(gg);
            float hv2 = sigm(go)*tanhf(cv);
            c_last = cv;
            size_t o = (size_t)(t+1)*BH_ + bg_c*H_ + u0 + cu;
            __stcg(&g_h[o], hv2);
            __stcg(&g_c[o], cv);
            float mv = __ldg(&mask[bg_c*T_ + t]);
            float hm = hv2*mv;
            out[(size_t)bg_c*(T_*H_) + (size_t)t*H_ + u0 + cu] = hm;
            hmx = fmaxf(hmx, hm);
            cmx = fmaxf(cmx, cv*mv);
            if(t+1 < T_){
                // push fresh h to all 8 CTAs' ring slot (t+1)%3
                u32 la = (u32)__cvta_generic_to_shared(
                    &fbuf[(t+1)%3][cb*272 + rank*34 + cu]);
#pragma unroll
                for(int r2=0;r2<8;r2++) st_cluster_f32(la, r2, hv2);
                // c prefetch for step t+1 (same-thread history; always visible)
                int f   = __ldg(&father[bg_c*T_ + t+1]);
                int idx = min(f, t) + 1;
                cfl = (idx == t+1);
                if(!cfl) c_pf = __ldcg(&g_c[(size_t)idx*BH_ + bg_c*H_ + u0 + cu]);
            }
        }
        if(t < T_-1) CARRIVE();   // (9) release pushes + stores
    }

    if(tid < 128){
        size_t base = (size_t)2*B_*T_*H_;
        out[base +       bg_c*H_ + u0 + cu] = hmx;   // h_max
        out[base + BH_ + bg_c*H_ + u0 + cu] = cmx;   // c_max
    }
}

extern "C" void kernel_launch(void* const* d_in, const int* in_sizes, int n_in,
                              void* d_out, int out_size)
{
    const int*   node   = (const int*)  d_in[0];
    const int*   rel    = (const int*)  d_in[1];
    const int*   father = (const int*)  d_in[2];
    const float* mask   = (const float*)d_in[3];
    const float* emb    = (const float*)d_in[4];
    const float* W_ih   = (const float*)d_in[5];
    const float* W_hh   = (const float*)d_in[6];
    const float* b_ih   = (const float*)d_in[7];
    const float* b_hh   = (const float*)d_in[8];
    const float* W_h    = (const float*)d_in[9];
    float* out = (float*)d_out;

    float *px, *pgx;
    cudaGetSymbolAddress((void**)&px,  g_x);
    cudaGetSymbolAddress((void**)&pgx, g_gx);

    embed_kernel<<<(B_*T_)/4, 128>>>(node, rel, emb);

    dim3 g1(G_/128, (B_*T_)/128);
    sgemm_nt<<<g1, 256>>>(px, W_ih, b_ih, pgx, B_*T_, G_, 256);

    scan_kernel<<<128, 256>>>(father, mask, W_hh, b_hh, out);

    dim3 g2(H_/128, (B_*T_)/128);
    sgemm_nt<<<g2, 256>>>(out, W_h, (const float*)nullptr,
                          out + (size_t)B_*T_*H_, B_*T_, H_, 256);
}